// round 4
// baseline (speedup 1.0000x reference)
#include <cuda_runtime.h>

// LDSMIXTURELQR: sequential nonlinear scan, T=131072 steps.
// Warp-specialized single-block kernel:
//   warp0 lane0   : the sequential recurrence (latency-bound, f32x2 packed math)
//   warp0 lanes1+ : idle (exit after init barrier)
//   warp1         : input producer  (GMEM -> SMEM ring, stores NEGATED xstar)
//   warp2         : output drainer  (SMEM ring -> GMEM)   [tid >= 64 ONLY]

#define CH    128
#define NSLOT 8

typedef unsigned long long u64;

__device__ __forceinline__ u64 pk2(float lo, float hi) {
    u64 r; asm("mov.b64 %0,{%1,%2};" : "=l"(r) : "f"(lo), "f"(hi)); return r;
}
__device__ __forceinline__ void upk2(u64 v, float& lo, float& hi) {
    asm("mov.b64 {%0,%1},%2;" : "=f"(lo), "=f"(hi) : "l"(v));
}
__device__ __forceinline__ u64 f2add(u64 a, u64 b) {
    u64 r; asm("add.rn.f32x2 %0,%1,%2;" : "=l"(r) : "l"(a), "l"(b)); return r;
}
__device__ __forceinline__ u64 f2mul(u64 a, u64 b) {
    u64 r; asm("mul.rn.f32x2 %0,%1,%2;" : "=l"(r) : "l"(a), "l"(b)); return r;
}
__device__ __forceinline__ u64 f2fma(u64 a, u64 b, u64 c) {
    u64 r; asm("fma.rn.f32x2 %0,%1,%2,%3;" : "=l"(r) : "l"(a), "l"(b), "l"(c)); return r;
}
__device__ __forceinline__ float ex2a(float x) {
    float r; asm("ex2.approx.f32 %0,%1;" : "=f"(r) : "f"(x)); return r;
}
__device__ __forceinline__ float rcpa(float x) {
    float r; asm("rcp.approx.f32 %0,%1;" : "=f"(r) : "f"(x)); return r;
}
__device__ __forceinline__ float sqrta(float x) {
    float r; asm("sqrt.approx.f32 %0,%1;" : "=f"(r) : "f"(x)); return r;
}

__global__ void __launch_bounds__(96, 1) LDSMIXTURELQR_58445914964044_kernel(
    const float* __restrict__ xs1, const float* __restrict__ xs2,
    const float* __restrict__ init_y, const float* __restrict__ x0p,
    const float* __restrict__ Ap, const float* __restrict__ Bp,
    const float* __restrict__ g1p, const float* __restrict__ g2p,
    float* __restrict__ out, int T)
{
    __shared__ __align__(16) float s_in1[NSLOT][CH * 2];  // negated xs1 chunk
    __shared__ __align__(16) float s_in2[NSLOT][CH * 2];  // negated xs2 chunk
    __shared__ __align__(16) float s_ox[NSLOT][CH];
    __shared__ __align__(16) float s_oy[NSLOT][CH * 2];
    __shared__ __align__(16) float s_ou[NSLOT][CH * 2];
    __shared__ volatile int f_in_ready[NSLOT];
    __shared__ volatile int f_in_done[NSLOT];
    __shared__ volatile int f_out_ready[NSLOT];
    __shared__ volatile int f_out_done[NSLOT];

    const int tid = threadIdx.x;
    if (tid < NSLOT) {
        f_in_ready[tid] = 0; f_in_done[tid] = 0;
        f_out_ready[tid] = 0; f_out_done[tid] = 0;
    }
    __syncthreads();

    const int nchunk = (T + CH - 1) / CH;

    if (tid == 0) {
        // ---------------- consumer: the sequential recurrence ----------------
        float x  = *x0p;
        float y0 = init_y[0], y1 = init_y[1];
        float A_ = *Ap;
        float s_ = Bp[0] + Bp[1];
        float g1 = *g1p, g2 = *g2p;
        const float dt = 1.0f / 60.0f;
        const float L2E  =  1.4426950408889634f;   //  log2(e)
        const float NL2E = -1.4426950408889634f;   // -log2(e)

        u64 yv   = pk2(y0, y1);
        u64 dtv  = pk2(dt, dt);
        u64 mg1v = pk2(-g1, -g1);
        u64 mg2v = pk2(-g2, -g2);

        // initial sigmoid pair from x0 (clipped)
        float xc = fminf(fmaxf(x, -10.0f), 10.0f);
        float w   = rcpa(1.0f + ex2a(xc * NL2E));  // sigmoid(xc)
        float omw = rcpa(1.0f + ex2a(xc * L2E));   // sigmoid(-xc) = 1-w
        float ax = A_ * x;

        for (int c = 0; c < nchunk; c++) {
            const int slot = c & (NSLOT - 1);
            while (f_in_ready[slot] < c + 1) {}
            if (c >= NSLOT) { while (f_out_done[slot] < c - NSLOT + 1) {} }
            __threadfence_block();

            const int len = min(CH, T - c * CH);
            const u64* p1 = (const u64*)s_in1[slot];
            const u64* p2 = (const u64*)s_in2[slot];
            float* ox = s_ox[slot];
            u64*   oy = (u64*)s_oy[slot];
            u64*   ou = (u64*)s_ou[slot];

            #pragma unroll 8
            for (int i = 0; i < len; i++) {
                const u64 nx1 = p1[i];               // -xs1_t (packed)
                const u64 nx2 = p2[i];               // -xs2_t
                const u64 e1  = f2add(yv, nx1);      // y - xs1
                const u64 e2  = f2add(yv, nx2);      // y - xs2
                const u64 av  = f2mul(mg1v, e1);     // -g1*e1
                const u64 bv  = f2mul(mg2v, e2);     // -g2*e2
                const u64 wv  = pk2(w, w);
                const u64 owv = pk2(omw, omw);
                const u64 uu  = f2add(f2mul(av, wv), f2mul(bv, owv)); // u_t
                yv = f2add(yv, f2mul(dtv, uu));      // y_{t+1} (match ref rounding)

                const u64 pp = f2mul(e1, e1);
                float plo, phi; upk2(pp, plo, phi);
                const float sq = plo + phi;
                const float n1 = sqrta(sq);
                const float xn = fmaf(s_, n1, ax);   // x_{t+1}
                ax = A_ * xn;
                const float xcn = fminf(fmaxf(xn, -10.0f), 10.0f);
                const float en  = ex2a(xcn * NL2E);  // exp(-xc)
                const float ep  = ex2a(xcn * L2E);   // exp(+xc)
                w   = rcpa(1.0f + en);               // sigmoid for t+1
                omw = rcpa(1.0f + ep);               // 1 - sigmoid for t+1

                ox[i] = xn;
                oy[i] = yv;
                ou[i] = uu;
            }
            __threadfence_block();
            f_out_ready[slot] = c + 1;
            f_in_done[slot]   = c + 1;
        }
    } else if (tid >= 32 && tid < 64) {
        // ---------------- producer: GMEM -> SMEM input ring ------------------
        const int lane = tid - 32;
        for (int c = 0; c < nchunk; c++) {
            const int slot = c & (NSLOT - 1);
            if (c >= NSLOT) { while (f_in_done[slot] < c - NSLOT + 1) {} }
            const int base = c * CH;
            const int len  = min(CH, T - base);
            if (len == CH) {
                const float4* g1v = (const float4*)(xs1 + (size_t)base * 2);
                const float4* g2v = (const float4*)(xs2 + (size_t)base * 2);
                float4* sm1 = (float4*)s_in1[slot];
                float4* sm2 = (float4*)s_in2[slot];
                #pragma unroll
                for (int k = lane; k < CH / 2; k += 32) {
                    float4 v = __ldg(&g1v[k]);
                    v.x = -v.x; v.y = -v.y; v.z = -v.z; v.w = -v.w;
                    sm1[k] = v;
                    float4 w4 = __ldg(&g2v[k]);
                    w4.x = -w4.x; w4.y = -w4.y; w4.z = -w4.z; w4.w = -w4.w;
                    sm2[k] = w4;
                }
            } else {
                for (int k = lane; k < len * 2; k += 32) {
                    s_in1[slot][k] = -xs1[(size_t)base * 2 + k];
                    s_in2[slot][k] = -xs2[(size_t)base * 2 + k];
                }
            }
            __threadfence_block();
            __syncwarp();
            if (lane == 0) f_in_ready[slot] = c + 1;
        }
    } else if (tid >= 64) {
        // ---------------- drainer: SMEM output ring -> GMEM ------------------
        // NOTE: predicate MUST be tid >= 64. Previous rounds used a bare `else`
        // which caught tids 1..31 (lane = tid-64 < 0) and corrupted the output
        // with negative-index strided writes.
        const int lane = tid - 64;
        const int TP1 = T + 1;
        if (lane == 0) {
            out[0]       = *x0p;        // x_full[0]
            out[TP1]     = init_y[0];   // y_full[0]
            out[TP1 + 1] = init_y[1];
        }
        float* outx = out + 1;                 // x_full[1+t]
        float* outy = out + TP1 + 2;           // y_full[1+t]
        float* outu = out + 3 * TP1;           // us[t]
        for (int c = 0; c < nchunk; c++) {
            const int slot = c & (NSLOT - 1);
            while (f_out_ready[slot] < c + 1) {}
            __threadfence_block();
            const int base = c * CH;
            const int len  = min(CH, T - base);
            for (int k = lane; k < len;     k += 32) outx[base + k]     = s_ox[slot][k];
            for (int k = lane; k < 2 * len; k += 32) outy[2 * base + k] = s_oy[slot][k];
            for (int k = lane; k < 2 * len; k += 32) outu[2 * base + k] = s_ou[slot][k];
            __syncwarp();
            if (lane == 0) f_out_done[slot] = c + 1;
        }
    }
    // tids 1..31: idle after init barrier (no further block-wide syncs).
}

extern "C" void kernel_launch(void* const* d_in, const int* in_sizes, int n_in,
                              void* d_out, int out_size) {
    // Input order confirmed declared: [xstar1, xstar2, init_y, x0, A, B, gain1, gain2]
    const float* xs1    = (const float*)d_in[0];
    const float* xs2    = (const float*)d_in[1];
    const float* init_y = (const float*)d_in[2];
    const float* x0     = (const float*)d_in[3];
    const float* A      = (const float*)d_in[4];
    const float* B      = (const float*)d_in[5];
    const float* g1     = (const float*)d_in[6];
    const float* g2     = (const float*)d_in[7];
    const int T = in_sizes[0] / 2;
    LDSMIXTURELQR_58445914964044_kernel<<<1, 96>>>(
        xs1, xs2, init_y, x0, A, B, g1, g2, (float*)d_out, T);
}

// round 5
// speedup vs baseline: 1.1837x; 1.1837x over previous
#include <cuda_runtime.h>

// LDSMIXTURELQR: sequential nonlinear scan, T=131072 steps.
// Warp-specialized single-block kernel:
//   warp0 lane0   : the sequential recurrence (latency-bound, f32x2 packed math)
//   warp0 lanes1+ : idle (exit after init barrier)
//   warp1         : input producer  (GMEM -> SMEM ring, stores NEGATED xstar)
//   warp2         : output drainer  (SMEM ring -> GMEM)   [tid >= 64 ONLY]
//
// Per-step math (chain-optimized, precision-preserving):
//   w  = 1/(1+exp2(z)),  z = -x*log2(e)  carried as its own linear recurrence
//   u  = (-g2*e2) + w*(g2*e2 - g1*e1)      [identical to w*(-g1e1)+(1-w)(-g2e2)]
//   n1 = sqrt(e1.e1)                        [sqrt.approx]
//   x' = A*x + (B0+B1)*n1 ;  z' = A*z + (B0+B1)*(-log2e)*n1 ;  y' = y + u/60
//   clip dropped: only perturbs w by <5e-5 when |x|>10 (system attenuates ~0.1x)

#define CH    256
#define NSLOT 4

typedef unsigned long long u64;

__device__ __forceinline__ u64 pk2(float lo, float hi) {
    u64 r; asm("mov.b64 %0,{%1,%2};" : "=l"(r) : "f"(lo), "f"(hi)); return r;
}
__device__ __forceinline__ void upk2(u64 v, float& lo, float& hi) {
    asm("mov.b64 {%0,%1},%2;" : "=f"(lo), "=f"(hi) : "l"(v));
}
__device__ __forceinline__ u64 f2add(u64 a, u64 b) {
    u64 r; asm("add.rn.f32x2 %0,%1,%2;" : "=l"(r) : "l"(a), "l"(b)); return r;
}
__device__ __forceinline__ u64 f2mul(u64 a, u64 b) {
    u64 r; asm("mul.rn.f32x2 %0,%1,%2;" : "=l"(r) : "l"(a), "l"(b)); return r;
}
__device__ __forceinline__ u64 f2fma(u64 a, u64 b, u64 c) {
    u64 r; asm("fma.rn.f32x2 %0,%1,%2,%3;" : "=l"(r) : "l"(a), "l"(b), "l"(c)); return r;
}
__device__ __forceinline__ float ex2a(float x) {
    float r; asm("ex2.approx.f32 %0,%1;" : "=f"(r) : "f"(x)); return r;
}
__device__ __forceinline__ float rcpa(float x) {
    float r; asm("rcp.approx.f32 %0,%1;" : "=f"(r) : "f"(x)); return r;
}
__device__ __forceinline__ float sqrta(float x) {
    float r; asm("sqrt.approx.f32 %0,%1;" : "=f"(r) : "f"(x)); return r;
}

__global__ void __launch_bounds__(96, 1) LDSMIXTURELQR_58445914964044_kernel(
    const float* __restrict__ xs1, const float* __restrict__ xs2,
    const float* __restrict__ init_y, const float* __restrict__ x0p,
    const float* __restrict__ Ap, const float* __restrict__ Bp,
    const float* __restrict__ g1p, const float* __restrict__ g2p,
    float* __restrict__ out, int T)
{
    __shared__ __align__(16) float s_in1[NSLOT][CH * 2];  // negated xs1 chunk
    __shared__ __align__(16) float s_in2[NSLOT][CH * 2];  // negated xs2 chunk
    __shared__ __align__(16) float s_ox[NSLOT][CH];
    __shared__ __align__(16) float s_oy[NSLOT][CH * 2];
    __shared__ __align__(16) float s_ou[NSLOT][CH * 2];
    __shared__ volatile int f_in_ready[NSLOT];
    __shared__ volatile int f_in_done[NSLOT];
    __shared__ volatile int f_out_ready[NSLOT];
    __shared__ volatile int f_out_done[NSLOT];

    const int tid = threadIdx.x;
    if (tid < NSLOT) {
        f_in_ready[tid] = 0; f_in_done[tid] = 0;
        f_out_ready[tid] = 0; f_out_done[tid] = 0;
    }
    __syncthreads();

    const int nchunk = (T + CH - 1) / CH;

    if (tid == 0) {
        // ---------------- consumer: the sequential recurrence ----------------
        float x  = *x0p;
        float y0 = init_y[0], y1 = init_y[1];
        float A_ = *Ap;
        float s_ = Bp[0] + Bp[1];
        float g1 = *g1p, g2 = *g2p;
        const float dt   = 1.0f / 60.0f;
        const float NL2E = -1.4426950408889634f;   // -log2(e)
        const float sN   = s_ * NL2E;

        u64 yv   = pk2(y0, y1);
        u64 dtv  = pk2(dt, dt);
        u64 mg1v = pk2(-g1, -g1);
        u64 mg2v = pk2(-g2, -g2);
        u64 g2v  = pk2( g2,  g2);

        // initial carried state from x0
        float z  = x * NL2E;              // -x*log2e
        float w  = rcpa(1.0f + ex2a(z));  // sigmoid(x0)  (|x0|<=10 w.h.p.; clip-free)
        u64   wv = pk2(w, w);
        float ax = A_ * x;                // A*x   (for x recurrence)
        float az = A_ * z;                // A*z   (for z recurrence)

        for (int c = 0; c < nchunk; c++) {
            const int slot = c & (NSLOT - 1);
            while (f_in_ready[slot] < c + 1) {}
            if (c >= NSLOT) { while (f_out_done[slot] < c - NSLOT + 1) {} }
            __threadfence_block();

            const int len = min(CH, T - c * CH);
            const u64* p1 = (const u64*)s_in1[slot];
            const u64* p2 = (const u64*)s_in2[slot];
            float* ox = s_ox[slot];
            u64*   oy = (u64*)s_oy[slot];
            u64*   ou = (u64*)s_ou[slot];

            #pragma unroll 8
            for (int i = 0; i < len; i++) {
                const u64 nx1 = p1[i];                // -xs1_t (packed)
                const u64 nx2 = p2[i];                // -xs2_t
                const u64 e1  = f2add(yv, nx1);       // y - xs1
                const u64 e2  = f2add(yv, nx2);       // y - xs2
                const u64 pv  = f2mul(g2v,  e2);      //  g2*e2
                const u64 bv  = f2mul(mg2v, e2);      // -g2*e2
                const u64 dv  = f2fma(mg1v, e1, pv);  //  g2*e2 - g1*e1
                const u64 uu  = f2fma(wv, dv, bv);    //  u_t
                yv = f2fma(dtv, uu, yv);              //  y_{t+1}

                float e1lo, e1hi; upk2(e1, e1lo, e1hi);           // reg-pair alias
                const float hh = e1hi * e1hi;
                const float sq = fmaf(e1lo, e1lo, hh);
                const float n1 = sqrta(sq);
                const float xn = fmaf(s_, n1, ax);    // x_{t+1}
                const float zn = fmaf(sN, n1, az);    // -x_{t+1}*log2e
                ax = A_ * xn;
                az = A_ * zn;
                const float en = ex2a(zn);            // exp(-x_{t+1})
                w  = rcpa(1.0f + en);                 // sigmoid(x_{t+1})
                wv = pk2(w, w);

                ox[i] = xn;
                oy[i] = yv;
                ou[i] = uu;
            }
            __threadfence_block();
            f_out_ready[slot] = c + 1;
            f_in_done[slot]   = c + 1;
        }
    } else if (tid >= 32 && tid < 64) {
        // ---------------- producer: GMEM -> SMEM input ring ------------------
        const int lane = tid - 32;
        for (int c = 0; c < nchunk; c++) {
            const int slot = c & (NSLOT - 1);
            if (c >= NSLOT) { while (f_in_done[slot] < c - NSLOT + 1) {} }
            const int base = c * CH;
            const int len  = min(CH, T - base);
            if (len == CH) {
                const float4* g1v4 = (const float4*)(xs1 + (size_t)base * 2);
                const float4* g2v4 = (const float4*)(xs2 + (size_t)base * 2);
                float4* sm1 = (float4*)s_in1[slot];
                float4* sm2 = (float4*)s_in2[slot];
                #pragma unroll
                for (int k = lane; k < CH / 2; k += 32) {
                    float4 v = __ldg(&g1v4[k]);
                    v.x = -v.x; v.y = -v.y; v.z = -v.z; v.w = -v.w;
                    sm1[k] = v;
                    float4 w4 = __ldg(&g2v4[k]);
                    w4.x = -w4.x; w4.y = -w4.y; w4.z = -w4.z; w4.w = -w4.w;
                    sm2[k] = w4;
                }
            } else {
                for (int k = lane; k < len * 2; k += 32) {
                    s_in1[slot][k] = -xs1[(size_t)base * 2 + k];
                    s_in2[slot][k] = -xs2[(size_t)base * 2 + k];
                }
            }
            __threadfence_block();
            __syncwarp();
            if (lane == 0) f_in_ready[slot] = c + 1;
        }
    } else if (tid >= 64) {
        // ---------------- drainer: SMEM output ring -> GMEM ------------------
        // predicate MUST be tid >= 64 (lanes 1..31 of warp0 idle elsewhere)
        const int lane = tid - 64;
        const int TP1 = T + 1;
        if (lane == 0) {
            out[0]       = *x0p;        // x_full[0]
            out[TP1]     = init_y[0];   // y_full[0]
            out[TP1 + 1] = init_y[1];
        }
        float* outx = out + 1;                 // x_full[1+t]
        float* outy = out + TP1 + 2;           // y_full[1+t]
        float* outu = out + 3 * TP1;           // us[t]
        for (int c = 0; c < nchunk; c++) {
            const int slot = c & (NSLOT - 1);
            while (f_out_ready[slot] < c + 1) {}
            __threadfence_block();
            const int base = c * CH;
            const int len  = min(CH, T - base);
            for (int k = lane; k < len;     k += 32) outx[base + k]     = s_ox[slot][k];
            for (int k = lane; k < 2 * len; k += 32) outy[2 * base + k] = s_oy[slot][k];
            for (int k = lane; k < 2 * len; k += 32) outu[2 * base + k] = s_ou[slot][k];
            __syncwarp();
            if (lane == 0) f_out_done[slot] = c + 1;
        }
    }
    // tids 1..31: idle after init barrier (no further block-wide syncs).
}

extern "C" void kernel_launch(void* const* d_in, const int* in_sizes, int n_in,
                              void* d_out, int out_size) {
    // Input order (confirmed): [xstar1, xstar2, init_y, x0, A, B, gain1, gain2]
    const float* xs1    = (const float*)d_in[0];
    const float* xs2    = (const float*)d_in[1];
    const float* init_y = (const float*)d_in[2];
    const float* x0     = (const float*)d_in[3];
    const float* A      = (const float*)d_in[4];
    const float* B      = (const float*)d_in[5];
    const float* g1     = (const float*)d_in[6];
    const float* g2     = (const float*)d_in[7];
    const int T = in_sizes[0] / 2;
    LDSMIXTURELQR_58445914964044_kernel<<<1, 96>>>(
        xs1, xs2, init_y, x0, A, B, g1, g2, (float*)d_out, T);
}

// round 6
// speedup vs baseline: 1.7061x; 1.4413x over previous
#include <cuda_runtime.h>
#include <math.h>

// LDSMIXTURELQR: sequential nonlinear scan, T=131072 steps.
// Warp-specialized single-block kernel:
//   warp0 lane0   : the sequential recurrence (latency-bound, f32x2 packed math)
//   warp0 lanes1+ : idle (exit after init barrier)
//   warp1         : input producer  (GMEM -> SMEM ring, stores NEGATED xstar)
//   warp2         : output drainer  (SMEM ring -> GMEM)   [tid >= 64 ONLY]
//
// Per-step math (single-MUFU-sigmoid, chain-optimized):
//   w  = 0.5 + 0.5*tanh(x/2)   [tanh.approx: |dw| <= 2.5e-4/step; measured
//                               closed-loop amplification ~O(1) => final ~1e-4]
//   u  = cv + th*hv,  hv = 0.5*(g2*e2 - g1*e1),  cv = -g2*e2 + hv   [exact identity]
//   n1 = sqrt(e1.e1)  [sqrt.approx]
//   x' = A*x + s*n1 ;  h' = A*h + (s/2)*n1  (h = x/2 carried) ;  y' = y + u/60

#define CH    256
#define NSLOT 4

typedef unsigned long long u64;

__device__ __forceinline__ u64 pk2(float lo, float hi) {
    u64 r; asm("mov.b64 %0,{%1,%2};" : "=l"(r) : "f"(lo), "f"(hi)); return r;
}
__device__ __forceinline__ void upk2(u64 v, float& lo, float& hi) {
    asm("mov.b64 {%0,%1},%2;" : "=f"(lo), "=f"(hi) : "l"(v));
}
__device__ __forceinline__ u64 f2add(u64 a, u64 b) {
    u64 r; asm("add.rn.f32x2 %0,%1,%2;" : "=l"(r) : "l"(a), "l"(b)); return r;
}
__device__ __forceinline__ u64 f2mul(u64 a, u64 b) {
    u64 r; asm("mul.rn.f32x2 %0,%1,%2;" : "=l"(r) : "l"(a), "l"(b)); return r;
}
__device__ __forceinline__ u64 f2fma(u64 a, u64 b, u64 c) {
    u64 r; asm("fma.rn.f32x2 %0,%1,%2,%3;" : "=l"(r) : "l"(a), "l"(b), "l"(c)); return r;
}
__device__ __forceinline__ float sqrta(float x) {
    float r; asm("sqrt.approx.f32 %0,%1;" : "=f"(r) : "f"(x)); return r;
}
__device__ __forceinline__ float tanha(float x) {
    float r; asm("tanh.approx.f32 %0,%1;" : "=f"(r) : "f"(x)); return r;
}

__global__ void __launch_bounds__(96, 1) LDSMIXTURELQR_58445914964044_kernel(
    const float* __restrict__ xs1, const float* __restrict__ xs2,
    const float* __restrict__ init_y, const float* __restrict__ x0p,
    const float* __restrict__ Ap, const float* __restrict__ Bp,
    const float* __restrict__ g1p, const float* __restrict__ g2p,
    float* __restrict__ out, int T)
{
    __shared__ __align__(16) float s_in1[NSLOT][CH * 2];  // negated xs1 chunk
    __shared__ __align__(16) float s_in2[NSLOT][CH * 2];  // negated xs2 chunk
    __shared__ __align__(16) float s_ox[NSLOT][CH];
    __shared__ __align__(16) float s_oy[NSLOT][CH * 2];
    __shared__ __align__(16) float s_ou[NSLOT][CH * 2];
    __shared__ volatile int f_in_ready[NSLOT];
    __shared__ volatile int f_in_done[NSLOT];
    __shared__ volatile int f_out_ready[NSLOT];
    __shared__ volatile int f_out_done[NSLOT];

    const int tid = threadIdx.x;
    if (tid < NSLOT) {
        f_in_ready[tid] = 0; f_in_done[tid] = 0;
        f_out_ready[tid] = 0; f_out_done[tid] = 0;
    }
    __syncthreads();

    const int nchunk = (T + CH - 1) / CH;

    if (tid == 0) {
        // ---------------- consumer: the sequential recurrence ----------------
        float x  = *x0p;
        float y0 = init_y[0], y1 = init_y[1];
        float A_ = *Ap;
        float s_ = Bp[0] + Bp[1];
        float g1 = *g1p, g2 = *g2p;
        const float dt = 1.0f / 60.0f;
        const float hS = 0.5f * s_;

        u64 yv    = pk2(y0, y1);
        u64 dtv   = pk2(dt, dt);
        u64 mhg1v = pk2(-0.5f * g1, -0.5f * g1);  // -g1/2
        u64 hg2v  = pk2( 0.5f * g2,  0.5f * g2);  //  g2/2
        u64 mg2v  = pk2(-g2, -g2);                // -g2

        // initial carried state from x0 (exact sigmoid once)
        float xc0 = fminf(fmaxf(x, -10.0f), 10.0f);
        float w0  = 1.0f / (1.0f + expf(-xc0));
        float th  = 2.0f * w0 - 1.0f;             // tanh(x0/2)
        float ax  = A_ * x;                       // A*x
        float ah  = 0.5f * ax;                    // A*(x/2)

        for (int c = 0; c < nchunk; c++) {
            const int slot = c & (NSLOT - 1);
            while (f_in_ready[slot] < c + 1) {}
            if (c >= NSLOT) { while (f_out_done[slot] < c - NSLOT + 1) {} }
            __threadfence_block();

            const int len = min(CH, T - c * CH);
            const u64* p1 = (const u64*)s_in1[slot];
            const u64* p2 = (const u64*)s_in2[slot];
            float* ox = s_ox[slot];
            u64*   oy = (u64*)s_oy[slot];
            u64*   ou = (u64*)s_ou[slot];

            #pragma unroll 8
            for (int i = 0; i < len; i++) {
                const u64 nx1 = p1[i];                 // -xs1_t (packed)
                const u64 nx2 = p2[i];                 // -xs2_t
                const u64 e1  = f2add(yv, nx1);        // y - xs1
                const u64 e2  = f2add(yv, nx2);        // y - xs2
                const u64 t1  = f2mul(hg2v,  e2);      //  g2/2 * e2
                const u64 hv  = f2fma(mhg1v, e1, t1);  //  (g2 e2 - g1 e1)/2
                const u64 cv  = f2fma(mg2v,  e2, hv);  // -g2 e2 + hv
                const u64 thv = pk2(th, th);
                const u64 uu  = f2fma(thv, hv, cv);    //  u_t
                yv = f2fma(dtv, uu, yv);               //  y_{t+1}

                float e1lo, e1hi; upk2(e1, e1lo, e1hi);
                const float hh = e1hi * e1hi;
                const float sq = fmaf(e1lo, e1lo, hh);
                const float n1 = sqrta(sq);
                const float xn = fmaf(s_, n1, ax);     // x_{t+1}
                const float hn = fmaf(hS, n1, ah);     // x_{t+1}/2
                ax = A_ * xn;
                ah = A_ * hn;
                th = tanha(hn);                        // tanh(x_{t+1}/2)

                ox[i] = xn;
                oy[i] = yv;
                ou[i] = uu;
            }
            __threadfence_block();
            f_out_ready[slot] = c + 1;
            f_in_done[slot]   = c + 1;
        }
    } else if (tid >= 32 && tid < 64) {
        // ---------------- producer: GMEM -> SMEM input ring ------------------
        const int lane = tid - 32;
        for (int c = 0; c < nchunk; c++) {
            const int slot = c & (NSLOT - 1);
            if (c >= NSLOT) { while (f_in_done[slot] < c - NSLOT + 1) {} }
            const int base = c * CH;
            const int len  = min(CH, T - base);
            if (len == CH) {
                const float4* g1v4 = (const float4*)(xs1 + (size_t)base * 2);
                const float4* g2v4 = (const float4*)(xs2 + (size_t)base * 2);
                float4* sm1 = (float4*)s_in1[slot];
                float4* sm2 = (float4*)s_in2[slot];
                #pragma unroll
                for (int k = lane; k < CH / 2; k += 32) {
                    float4 v = __ldg(&g1v4[k]);
                    v.x = -v.x; v.y = -v.y; v.z = -v.z; v.w = -v.w;
                    sm1[k] = v;
                    float4 w4 = __ldg(&g2v4[k]);
                    w4.x = -w4.x; w4.y = -w4.y; w4.z = -w4.z; w4.w = -w4.w;
                    sm2[k] = w4;
                }
            } else {
                for (int k = lane; k < len * 2; k += 32) {
                    s_in1[slot][k] = -xs1[(size_t)base * 2 + k];
                    s_in2[slot][k] = -xs2[(size_t)base * 2 + k];
                }
            }
            __threadfence_block();
            __syncwarp();
            if (lane == 0) f_in_ready[slot] = c + 1;
        }
    } else if (tid >= 64) {
        // ---------------- drainer: SMEM output ring -> GMEM ------------------
        // predicate MUST be tid >= 64 (lanes 1..31 of warp0 idle elsewhere)
        const int lane = tid - 64;
        const int TP1 = T + 1;
        if (lane == 0) {
            out[0]       = *x0p;        // x_full[0]
            out[TP1]     = init_y[0];   // y_full[0]
            out[TP1 + 1] = init_y[1];
        }
        float* outx = out + 1;                 // x_full[1+t]
        float* outy = out + TP1 + 2;           // y_full[1+t]
        float* outu = out + 3 * TP1;           // us[t]
        for (int c = 0; c < nchunk; c++) {
            const int slot = c & (NSLOT - 1);
            while (f_out_ready[slot] < c + 1) {}
            __threadfence_block();
            const int base = c * CH;
            const int len  = min(CH, T - base);
            for (int k = lane; k < len;     k += 32) outx[base + k]     = s_ox[slot][k];
            for (int k = lane; k < 2 * len; k += 32) outy[2 * base + k] = s_oy[slot][k];
            for (int k = lane; k < 2 * len; k += 32) outu[2 * base + k] = s_ou[slot][k];
            __syncwarp();
            if (lane == 0) f_out_done[slot] = c + 1;
        }
    }
    // tids 1..31: idle after init barrier (no further block-wide syncs).
}

extern "C" void kernel_launch(void* const* d_in, const int* in_sizes, int n_in,
                              void* d_out, int out_size) {
    // Input order (confirmed): [xstar1, xstar2, init_y, x0, A, B, gain1, gain2]
    const float* xs1    = (const float*)d_in[0];
    const float* xs2    = (const float*)d_in[1];
    const float* init_y = (const float*)d_in[2];
    const float* x0     = (const float*)d_in[3];
    const float* A      = (const float*)d_in[4];
    const float* B      = (const float*)d_in[5];
    const float* g1     = (const float*)d_in[6];
    const float* g2     = (const float*)d_in[7];
    const int T = in_sizes[0] / 2;
    LDSMIXTURELQR_58445914964044_kernel<<<1, 96>>>(
        xs1, xs2, init_y, x0, A, B, g1, g2, (float*)d_out, T);
}

// round 7
// speedup vs baseline: 2.0257x; 1.1873x over previous
#include <cuda_runtime.h>
#include <math.h>

// LDSMIXTURELQR: sequential nonlinear scan, T=131072 steps.
// Warp-specialized single-block kernel:
//   warp0 lane0   : the sequential recurrence (latency-bound, f32x2 packed math)
//   warp0 lanes1+ : idle (exit after init barrier)
//   warp1         : input producer  (GMEM -> SMEM ring, stores NEGATED xstar)
//   warp2         : output drainer  (SMEM ring -> GMEM)   [tid >= 64 ONLY]
//
// R7 changes vs R6 (math identical):
//   - explicit distance-2 LDS prefetch in the consumer inner loop
//   - static-bound (len==CH) fast path for clean unrolling

#define CH    256
#define NSLOT 4

typedef unsigned long long u64;

__device__ __forceinline__ u64 pk2(float lo, float hi) {
    u64 r; asm("mov.b64 %0,{%1,%2};" : "=l"(r) : "f"(lo), "f"(hi)); return r;
}
__device__ __forceinline__ void upk2(u64 v, float& lo, float& hi) {
    asm("mov.b64 {%0,%1},%2;" : "=f"(lo), "=f"(hi) : "l"(v));
}
__device__ __forceinline__ u64 f2add(u64 a, u64 b) {
    u64 r; asm("add.rn.f32x2 %0,%1,%2;" : "=l"(r) : "l"(a), "l"(b)); return r;
}
__device__ __forceinline__ u64 f2mul(u64 a, u64 b) {
    u64 r; asm("mul.rn.f32x2 %0,%1,%2;" : "=l"(r) : "l"(a), "l"(b)); return r;
}
__device__ __forceinline__ u64 f2fma(u64 a, u64 b, u64 c) {
    u64 r; asm("fma.rn.f32x2 %0,%1,%2,%3;" : "=l"(r) : "l"(a), "l"(b), "l"(c)); return r;
}
__device__ __forceinline__ float sqrta(float x) {
    float r; asm("sqrt.approx.f32 %0,%1;" : "=f"(r) : "f"(x)); return r;
}
__device__ __forceinline__ float tanha(float x) {
    float r; asm("tanh.approx.f32 %0,%1;" : "=f"(r) : "f"(x)); return r;
}

__global__ void __launch_bounds__(96, 1) LDSMIXTURELQR_58445914964044_kernel(
    const float* __restrict__ xs1, const float* __restrict__ xs2,
    const float* __restrict__ init_y, const float* __restrict__ x0p,
    const float* __restrict__ Ap, const float* __restrict__ Bp,
    const float* __restrict__ g1p, const float* __restrict__ g2p,
    float* __restrict__ out, int T)
{
    __shared__ __align__(16) float s_in1[NSLOT][CH * 2];  // negated xs1 chunk
    __shared__ __align__(16) float s_in2[NSLOT][CH * 2];  // negated xs2 chunk
    __shared__ __align__(16) float s_ox[NSLOT][CH];
    __shared__ __align__(16) float s_oy[NSLOT][CH * 2];
    __shared__ __align__(16) float s_ou[NSLOT][CH * 2];
    __shared__ volatile int f_in_ready[NSLOT];
    __shared__ volatile int f_in_done[NSLOT];
    __shared__ volatile int f_out_ready[NSLOT];
    __shared__ volatile int f_out_done[NSLOT];

    const int tid = threadIdx.x;
    if (tid < NSLOT) {
        f_in_ready[tid] = 0; f_in_done[tid] = 0;
        f_out_ready[tid] = 0; f_out_done[tid] = 0;
    }
    __syncthreads();

    const int nchunk = (T + CH - 1) / CH;

    if (tid == 0) {
        // ---------------- consumer: the sequential recurrence ----------------
        float x  = *x0p;
        float y0 = init_y[0], y1 = init_y[1];
        float A_ = *Ap;
        float s_ = Bp[0] + Bp[1];
        float g1 = *g1p, g2 = *g2p;
        const float dt = 1.0f / 60.0f;
        const float hS = 0.5f * s_;

        u64 yv    = pk2(y0, y1);
        u64 dtv   = pk2(dt, dt);
        u64 mhg1v = pk2(-0.5f * g1, -0.5f * g1);  // -g1/2
        u64 hg2v  = pk2( 0.5f * g2,  0.5f * g2);  //  g2/2
        u64 mg2v  = pk2(-g2, -g2);                // -g2

        // initial carried state from x0 (exact sigmoid once)
        float xc0 = fminf(fmaxf(x, -10.0f), 10.0f);
        float w0  = 1.0f / (1.0f + expf(-xc0));
        float th  = 2.0f * w0 - 1.0f;             // tanh(x0/2)
        float ax  = A_ * x;                       // A*x
        float ah  = 0.5f * ax;                    // A*(x/2)

        for (int c = 0; c < nchunk; c++) {
            const int slot = c & (NSLOT - 1);
            while (f_in_ready[slot] < c + 1) {}
            if (c >= NSLOT) { while (f_out_done[slot] < c - NSLOT + 1) {} }
            __threadfence_block();

            const int len = min(CH, T - c * CH);
            const u64* p1 = (const u64*)s_in1[slot];
            const u64* p2 = (const u64*)s_in2[slot];
            float* ox = s_ox[slot];
            u64*   oy = (u64*)s_oy[slot];
            u64*   ou = (u64*)s_ou[slot];

            if (len == CH) {
                // fast path: static bounds + distance-2 LDS prefetch.
                // p1/p2 reads at i+2 go up to index CH+1, which lands in the
                // next SMEM array row — in-bounds of the shared block, harmless.
                u64 a1 = p1[0], a2 = p2[0];
                u64 b1 = p1[1], b2 = p2[1];
                #pragma unroll 8
                for (int i = 0; i < CH; i++) {
                    const u64 nx1 = a1;                    // -xs1_t (packed)
                    const u64 nx2 = a2;                    // -xs2_t
                    a1 = b1; a2 = b2;
                    b1 = p1[i + 2]; b2 = p2[i + 2];        // prefetch +2

                    const u64 e1  = f2add(yv, nx1);        // y - xs1
                    const u64 e2  = f2add(yv, nx2);        // y - xs2
                    const u64 t1  = f2mul(hg2v,  e2);      //  g2/2 * e2
                    const u64 hv  = f2fma(mhg1v, e1, t1);  //  (g2 e2 - g1 e1)/2
                    const u64 cv  = f2fma(mg2v,  e2, hv);  // -g2 e2 + hv
                    const u64 thv = pk2(th, th);
                    const u64 uu  = f2fma(thv, hv, cv);    //  u_t
                    yv = f2fma(dtv, uu, yv);               //  y_{t+1}

                    float e1lo, e1hi; upk2(e1, e1lo, e1hi);
                    const float hh = e1hi * e1hi;
                    const float sq = fmaf(e1lo, e1lo, hh);
                    const float n1 = sqrta(sq);
                    const float xn = fmaf(s_, n1, ax);     // x_{t+1}
                    const float hn = fmaf(hS, n1, ah);     // x_{t+1}/2
                    ax = A_ * xn;
                    ah = A_ * hn;
                    th = tanha(hn);                        // tanh(x_{t+1}/2)

                    ox[i] = xn;
                    oy[i] = yv;
                    ou[i] = uu;
                }
            } else {
                for (int i = 0; i < len; i++) {
                    const u64 nx1 = p1[i];
                    const u64 nx2 = p2[i];
                    const u64 e1  = f2add(yv, nx1);
                    const u64 e2  = f2add(yv, nx2);
                    const u64 t1  = f2mul(hg2v,  e2);
                    const u64 hv  = f2fma(mhg1v, e1, t1);
                    const u64 cv  = f2fma(mg2v,  e2, hv);
                    const u64 thv = pk2(th, th);
                    const u64 uu  = f2fma(thv, hv, cv);
                    yv = f2fma(dtv, uu, yv);

                    float e1lo, e1hi; upk2(e1, e1lo, e1hi);
                    const float hh = e1hi * e1hi;
                    const float sq = fmaf(e1lo, e1lo, hh);
                    const float n1 = sqrta(sq);
                    const float xn = fmaf(s_, n1, ax);
                    const float hn = fmaf(hS, n1, ah);
                    ax = A_ * xn;
                    ah = A_ * hn;
                    th = tanha(hn);

                    ox[i] = xn;
                    oy[i] = yv;
                    ou[i] = uu;
                }
            }
            __threadfence_block();
            f_out_ready[slot] = c + 1;
            f_in_done[slot]   = c + 1;
        }
    } else if (tid >= 32 && tid < 64) {
        // ---------------- producer: GMEM -> SMEM input ring ------------------
        const int lane = tid - 32;
        for (int c = 0; c < nchunk; c++) {
            const int slot = c & (NSLOT - 1);
            if (c >= NSLOT) { while (f_in_done[slot] < c - NSLOT + 1) {} }
            const int base = c * CH;
            const int len  = min(CH, T - base);
            if (len == CH) {
                const float4* g1v4 = (const float4*)(xs1 + (size_t)base * 2);
                const float4* g2v4 = (const float4*)(xs2 + (size_t)base * 2);
                float4* sm1 = (float4*)s_in1[slot];
                float4* sm2 = (float4*)s_in2[slot];
                #pragma unroll
                for (int k = lane; k < CH / 2; k += 32) {
                    float4 v = __ldg(&g1v4[k]);
                    v.x = -v.x; v.y = -v.y; v.z = -v.z; v.w = -v.w;
                    sm1[k] = v;
                    float4 w4 = __ldg(&g2v4[k]);
                    w4.x = -w4.x; w4.y = -w4.y; w4.z = -w4.z; w4.w = -w4.w;
                    sm2[k] = w4;
                }
            } else {
                for (int k = lane; k < len * 2; k += 32) {
                    s_in1[slot][k] = -xs1[(size_t)base * 2 + k];
                    s_in2[slot][k] = -xs2[(size_t)base * 2 + k];
                }
            }
            __threadfence_block();
            __syncwarp();
            if (lane == 0) f_in_ready[slot] = c + 1;
        }
    } else if (tid >= 64) {
        // ---------------- drainer: SMEM output ring -> GMEM ------------------
        // predicate MUST be tid >= 64 (lanes 1..31 of warp0 idle elsewhere)
        const int lane = tid - 64;
        const int TP1 = T + 1;
        if (lane == 0) {
            out[0]       = *x0p;        // x_full[0]
            out[TP1]     = init_y[0];   // y_full[0]
            out[TP1 + 1] = init_y[1];
        }
        float* outx = out + 1;                 // x_full[1+t]
        float* outy = out + TP1 + 2;           // y_full[1+t]
        float* outu = out + 3 * TP1;           // us[t]
        for (int c = 0; c < nchunk; c++) {
            const int slot = c & (NSLOT - 1);
            while (f_out_ready[slot] < c + 1) {}
            __threadfence_block();
            const int base = c * CH;
            const int len  = min(CH, T - base);
            for (int k = lane; k < len;     k += 32) outx[base + k]     = s_ox[slot][k];
            for (int k = lane; k < 2 * len; k += 32) outy[2 * base + k] = s_oy[slot][k];
            for (int k = lane; k < 2 * len; k += 32) outu[2 * base + k] = s_ou[slot][k];
            __syncwarp();
            if (lane == 0) f_out_done[slot] = c + 1;
        }
    }
    // tids 1..31: idle after init barrier (no further block-wide syncs).
}

extern "C" void kernel_launch(void* const* d_in, const int* in_sizes, int n_in,
                              void* d_out, int out_size) {
    // Input order (confirmed): [xstar1, xstar2, init_y, x0, A, B, gain1, gain2]
    const float* xs1    = (const float*)d_in[0];
    const float* xs2    = (const float*)d_in[1];
    const float* init_y = (const float*)d_in[2];
    const float* x0     = (const float*)d_in[3];
    const float* A      = (const float*)d_in[4];
    const float* B      = (const float*)d_in[5];
    const float* g1     = (const float*)d_in[6];
    const float* g2     = (const float*)d_in[7];
    const int T = in_sizes[0] / 2;
    LDSMIXTURELQR_58445914964044_kernel<<<1, 96>>>(
        xs1, xs2, init_y, x0, A, B, g1, g2, (float*)d_out, T);
}

// round 8
// speedup vs baseline: 2.2422x; 1.1069x over previous
#include <cuda_runtime.h>
#include <math.h>

// LDSMIXTURELQR: sequential nonlinear scan, T=131072 steps.
// Warp-specialized single-block kernel:
//   warp0 lane0   : the sequential recurrence (latency-bound)
//   warp1         : producer (GMEM -> SMEM ring, precomputes -xs1, qh, m)
//   warp2         : drainer  (SMEM ring -> GMEM)   [tid >= 64 ONLY]
//
// R8 algebra (exact identity with w=(1+th)/2, th=tanh(x/2)):
//   u_t = (m_t - c*y) + th*(qh_t - d*y)
//     c = (g1+g2)/2, d = (g1-g2)/2           (consumer constants)
//     m_t  = (g1*xs1_t + g2*xs2_t)/2          (producer-precomputed)
//     qh_t = (g1*xs1_t - g2*xs2_t)/2          (producer-precomputed)
//   e1_{t+1} = dt*u_t + (y_t + nx1_{t+1})     (chain-shortened error update)
//   n1 = sqrt(e1.e1); x' = A*x + s*n1; h' = A*h + (s/2)*n1; y' = y + dt*u

#define CH    256
#define NSLOT 4

typedef unsigned long long u64;

__device__ __forceinline__ u64 pk2(float lo, float hi) {
    u64 r; asm("mov.b64 %0,{%1,%2};" : "=l"(r) : "f"(lo), "f"(hi)); return r;
}
__device__ __forceinline__ void upk2(u64 v, float& lo, float& hi) {
    asm("mov.b64 {%0,%1},%2;" : "=f"(lo), "=f"(hi) : "l"(v));
}
__device__ __forceinline__ u64 f2add(u64 a, u64 b) {
    u64 r; asm("add.rn.f32x2 %0,%1,%2;" : "=l"(r) : "l"(a), "l"(b)); return r;
}
__device__ __forceinline__ u64 f2fma(u64 a, u64 b, u64 c) {
    u64 r; asm("fma.rn.f32x2 %0,%1,%2,%3;" : "=l"(r) : "l"(a), "l"(b), "l"(c)); return r;
}
__device__ __forceinline__ float sqrta(float x) {
    float r; asm("sqrt.approx.f32 %0,%1;" : "=f"(r) : "f"(x)); return r;
}
__device__ __forceinline__ float tanha(float x) {
    float r; asm("tanh.approx.f32 %0,%1;" : "=f"(r) : "f"(x)); return r;
}

__global__ void __launch_bounds__(96, 1) LDSMIXTURELQR_58445914964044_kernel(
    const float* __restrict__ xs1, const float* __restrict__ xs2,
    const float* __restrict__ init_y, const float* __restrict__ x0p,
    const float* __restrict__ Ap, const float* __restrict__ Bp,
    const float* __restrict__ g1p, const float* __restrict__ g2p,
    float* __restrict__ out, int T)
{
    // Array order matters: consumer prefetch overreads a few u64 past a row
    // end; they must land inside the shared block (next array), never OOB.
    __shared__ __align__(16) float s_nx1[NSLOT][CH * 2];   // -xs1 (packed pairs)
    __shared__ __align__(16) float s_qm [NSLOT][CH * 4];   // {qh0,qh1,m0,m1} per step
    __shared__ __align__(16) float s_ox [NSLOT][CH];       // x_{t+1}
    __shared__ __align__(16) float s_oyu[NSLOT][CH * 4];   // {y0,y1,u0,u1} per step
    __shared__ volatile int f_in_ready[NSLOT];
    __shared__ volatile int f_in_done[NSLOT];
    __shared__ volatile int f_out_ready[NSLOT];
    __shared__ volatile int f_out_done[NSLOT];

    const int tid = threadIdx.x;
    if (tid < NSLOT) {
        f_in_ready[tid] = 0; f_in_done[tid] = 0;
        f_out_ready[tid] = 0; f_out_done[tid] = 0;
    }
    __syncthreads();

    const int nchunk = (T + CH - 1) / CH;

    if (tid == 0) {
        // ---------------- consumer: the sequential recurrence ----------------
        float x  = *x0p;
        float y0 = init_y[0], y1 = init_y[1];
        float A_ = *Ap;
        float s_ = Bp[0] + Bp[1];
        float g1 = *g1p, g2 = *g2p;
        const float dt = 1.0f / 60.0f;
        const float hS = 0.5f * s_;
        const float c_ = 0.5f * (g1 + g2);
        const float dg = 0.5f * (g1 - g2);

        u64 yv   = pk2(y0, y1);
        u64 dtv  = pk2(dt, dt);
        u64 mcv  = pk2(-c_, -c_);
        u64 mdgv = pk2(-dg, -dg);

        // initial carried state from x0 (exact sigmoid once)
        float xc0 = fminf(fmaxf(x, -10.0f), 10.0f);
        float w0  = 1.0f / (1.0f + expf(-xc0));
        float th  = 2.0f * w0 - 1.0f;             // tanh(x0/2)
        float ax  = A_ * x;                       // A*x
        float ah  = 0.5f * ax;                    // A*(x/2)

        for (int c = 0; c < nchunk; c++) {
            const int slot = c & (NSLOT - 1);
            while (f_in_ready[slot] < c + 1) {}
            if (c >= NSLOT) { while (f_out_done[slot] < c - NSLOT + 1) {} }
            __threadfence_block();

            const int len = min(CH, T - c * CH);
            const u64*        pnx = (const u64*)s_nx1[slot];
            const ulonglong2* pqm = (const ulonglong2*)s_qm[slot];
            float*       ox  = s_ox[slot];
            ulonglong2*  oyu = (ulonglong2*)s_oyu[slot];

            if (len == CH) {
                // fresh e1 for first step of the chunk (overwrites any garbage
                // carried from the previous chunk's boundary overread)
                u64 e1p = f2add(yv, pnx[0]);
                float e1lo, e1hi; upk2(e1p, e1lo, e1hi);
                // prefetch pipeline (distance 2)
                u64        a_nx = pnx[1];   // nx1_{i+1} for i=0
                ulonglong2 a_qm = pqm[0];
                u64        b_nx = pnx[2];
                ulonglong2 b_qm = pqm[1];

                #pragma unroll 8
                for (int i = 0; i < CH; i++) {
                    const u64        nxn = a_nx;   // -xs1_{i+1}
                    const ulonglong2 qm  = a_qm;   // {qh_i, m_i}
                    a_nx = b_nx; a_qm = b_qm;
                    b_nx = pnx[i + 3];             // overreads land in s_qm: safe
                    b_qm = pqm[i + 2];             // overreads land in s_ox: safe

                    // ---- norm / x chain (critical) ----
                    const float hh = e1hi * e1hi;
                    const float sq = fmaf(e1lo, e1lo, hh);
                    const float n1 = sqrta(sq);
                    const float xn = fmaf(s_, n1, ax);   // x_{i+1}
                    const float hn = fmaf(hS, n1, ah);   // x_{i+1}/2

                    // ---- u_i = (m - c y) + th (qh - d y) ----
                    const u64 Qh = f2fma(mdgv, yv, qm.x);
                    const u64 P2 = f2fma(mcv,  yv, qm.y);
                    float qhlo, qhhi; upk2(Qh, qhlo, qhhi);
                    float p2lo, p2hi; upk2(P2, p2lo, p2hi);
                    const float ulo = fmaf(th, qhlo, p2lo);
                    const float uhi = fmaf(th, qhhi, p2hi);
                    const u64 uu = pk2(ulo, uhi);

                    // ---- next e1 (chain-shortened) ----
                    const u64 ply = f2add(yv, nxn);      // y_i - xs1_{i+1}
                    float pllo, plhi; upk2(ply, pllo, plhi);
                    e1lo = fmaf(dt, ulo, pllo);
                    e1hi = fmaf(dt, uhi, plhi);

                    // ---- state updates ----
                    yv = f2fma(dtv, uu, yv);             // y_{i+1}
                    ax = A_ * xn;
                    ah = A_ * hn;
                    th = tanha(hn);                      // tanh(x_{i+1}/2)

                    // ---- stores ----
                    ox[i] = xn;
                    ulonglong2 st; st.x = yv; st.y = uu;
                    oyu[i] = st;                         // STS.128
                }
            } else {
                // generic tail path (unused for T % CH == 0)
                for (int i = 0; i < len; i++) {
                    const u64 e1p = f2add(yv, pnx[i]);
                    float e1lo, e1hi; upk2(e1p, e1lo, e1hi);
                    const float hh = e1hi * e1hi;
                    const float sq = fmaf(e1lo, e1lo, hh);
                    const float n1 = sqrta(sq);
                    const float xn = fmaf(s_, n1, ax);
                    const float hn = fmaf(hS, n1, ah);
                    const ulonglong2 qm = pqm[i];
                    const u64 Qh = f2fma(mdgv, yv, qm.x);
                    const u64 P2 = f2fma(mcv,  yv, qm.y);
                    float qhlo, qhhi; upk2(Qh, qhlo, qhhi);
                    float p2lo, p2hi; upk2(P2, p2lo, p2hi);
                    const float ulo = fmaf(th, qhlo, p2lo);
                    const float uhi = fmaf(th, qhhi, p2hi);
                    const u64 uu = pk2(ulo, uhi);
                    yv = f2fma(dtv, uu, yv);
                    ax = A_ * xn;
                    ah = A_ * hn;
                    th = tanha(hn);
                    ox[i] = xn;
                    ulonglong2 st; st.x = yv; st.y = uu;
                    oyu[i] = st;
                }
            }
            __threadfence_block();
            f_out_ready[slot] = c + 1;
            f_in_done[slot]   = c + 1;
        }
    } else if (tid >= 32 && tid < 64) {
        // ---------------- producer: GMEM -> SMEM input ring ------------------
        const int lane = tid - 32;
        const float g1 = *g1p, g2 = *g2p;
        const float hg1 = 0.5f * g1, hg2 = 0.5f * g2;
        for (int c = 0; c < nchunk; c++) {
            const int slot = c & (NSLOT - 1);
            if (c >= NSLOT) { while (f_in_done[slot] < c - NSLOT + 1) {} }
            const int base = c * CH;
            const int len  = min(CH, T - base);
            if (len == CH) {
                const float4* g1v4 = (const float4*)(xs1 + (size_t)base * 2);
                const float4* g2v4 = (const float4*)(xs2 + (size_t)base * 2);
                float4* smn = (float4*)s_nx1[slot];
                float4* smq = (float4*)s_qm[slot];
                #pragma unroll
                for (int k = lane; k < CH / 2; k += 32) {   // k covers 2 steps
                    const float4 v1 = __ldg(&g1v4[k]);
                    const float4 v2 = __ldg(&g2v4[k]);
                    float4 n; n.x = -v1.x; n.y = -v1.y; n.z = -v1.z; n.w = -v1.w;
                    smn[k] = n;
                    float4 qa;  // step 2k: {qh0, qh1, m0, m1}
                    qa.x = hg1 * v1.x - hg2 * v2.x;
                    qa.y = hg1 * v1.y - hg2 * v2.y;
                    qa.z = hg1 * v1.x + hg2 * v2.x;
                    qa.w = hg1 * v1.y + hg2 * v2.y;
                    smq[2 * k] = qa;
                    float4 qb;  // step 2k+1
                    qb.x = hg1 * v1.z - hg2 * v2.z;
                    qb.y = hg1 * v1.w - hg2 * v2.w;
                    qb.z = hg1 * v1.z + hg2 * v2.z;
                    qb.w = hg1 * v1.w + hg2 * v2.w;
                    smq[2 * k + 1] = qb;
                }
            } else {
                for (int k = lane; k < len; k += 32) {
                    const float a0 = xs1[(size_t)(base + k) * 2];
                    const float a1 = xs1[(size_t)(base + k) * 2 + 1];
                    const float b0 = xs2[(size_t)(base + k) * 2];
                    const float b1 = xs2[(size_t)(base + k) * 2 + 1];
                    s_nx1[slot][2 * k]     = -a0;
                    s_nx1[slot][2 * k + 1] = -a1;
                    s_qm[slot][4 * k]     = hg1 * a0 - hg2 * b0;
                    s_qm[slot][4 * k + 1] = hg1 * a1 - hg2 * b1;
                    s_qm[slot][4 * k + 2] = hg1 * a0 + hg2 * b0;
                    s_qm[slot][4 * k + 3] = hg1 * a1 + hg2 * b1;
                }
            }
            __threadfence_block();
            __syncwarp();
            if (lane == 0) f_in_ready[slot] = c + 1;
        }
    } else if (tid >= 64) {
        // ---------------- drainer: SMEM output ring -> GMEM ------------------
        // predicate MUST be tid >= 64 (lanes 1..31 of warp0 idle elsewhere)
        const int lane = tid - 64;
        const int TP1 = T + 1;
        if (lane == 0) {
            out[0]       = *x0p;        // x_full[0]
            out[TP1]     = init_y[0];   // y_full[0]
            out[TP1 + 1] = init_y[1];
        }
        float* outx = out + 1;                 // x_full[1+t]
        float* outy = out + TP1 + 2;           // y_full[1+t]
        float* outu = out + 3 * TP1;           // us[t]
        for (int c = 0; c < nchunk; c++) {
            const int slot = c & (NSLOT - 1);
            while (f_out_ready[slot] < c + 1) {}
            __threadfence_block();
            const int base = c * CH;
            const int len  = min(CH, T - base);
            const float4* oyu4 = (const float4*)s_oyu[slot];
            for (int k = lane; k < len; k += 32) {
                const float4 v = oyu4[k];
                outy[2 * (base + k)]     = v.x;
                outy[2 * (base + k) + 1] = v.y;
                outu[2 * (base + k)]     = v.z;
                outu[2 * (base + k) + 1] = v.w;
            }
            for (int k = lane; k < len; k += 32) outx[base + k] = s_ox[slot][k];
            __syncwarp();
            if (lane == 0) f_out_done[slot] = c + 1;
        }
    }
    // tids 1..31: idle after init barrier (no further block-wide syncs).
}

extern "C" void kernel_launch(void* const* d_in, const int* in_sizes, int n_in,
                              void* d_out, int out_size) {
    // Input order (confirmed): [xstar1, xstar2, init_y, x0, A, B, gain1, gain2]
    const float* xs1    = (const float*)d_in[0];
    const float* xs2    = (const float*)d_in[1];
    const float* init_y = (const float*)d_in[2];
    const float* x0     = (const float*)d_in[3];
    const float* A      = (const float*)d_in[4];
    const float* B      = (const float*)d_in[5];
    const float* g1     = (const float*)d_in[6];
    const float* g2     = (const float*)d_in[7];
    const int T = in_sizes[0] / 2;
    LDSMIXTURELQR_58445914964044_kernel<<<1, 96>>>(
        xs1, xs2, init_y, x0, A, B, g1, g2, (float*)d_out, T);
}

// round 10
// speedup vs baseline: 2.3556x; 1.0506x over previous
#include <cuda_runtime.h>
#include <math.h>

// LDSMIXTURELQR: sequential nonlinear scan, T=131072 steps.
// 4-warp specialization (128 threads):
//   warp0 lane0 : serial core — minimal recurrence, stores {u0,u1,n1} per step
//   warp1       : producer — GMEM -> SMEM ring (-xs1, qh, m precomputed)
//   warp2       : lane0 reconstructs x from n1 (bit-identical) + STG;
//                 lanes 1-31 copy u SMEM -> GMEM (scalar: us base is odd-offset)
//   warp3       : lane0 reconstructs y from u (bit-identical f2fma) + STG.32 x2
//
// NOTE on alignment: y_full starts at out+(T+1), us at out+3(T+1) — both ODD
// float offsets for even T. All GMEM stores to these regions must be 32-bit.
//
// Serial-core algebra (exact identity with w=(1+th)/2, th=tanh(x/2)):
//   u_t = (m_t - c*y) + th*(qh_t - d*y);  c=(g1+g2)/2, d=(g1-g2)/2
//   e1_{t+1} = dt*u_t + (y_t - xs1_{t+1});  n1 = sqrt(e1.e1)
//   h' = A*h + (s/2)*n1  (h = x/2; exact power-of-2 scaling of the x chain)

#define CH    256
#define NSLOT 4

typedef unsigned long long u64;

__device__ __forceinline__ u64 pk2(float lo, float hi) {
    u64 r; asm("mov.b64 %0,{%1,%2};" : "=l"(r) : "f"(lo), "f"(hi)); return r;
}
__device__ __forceinline__ void upk2(u64 v, float& lo, float& hi) {
    asm("mov.b64 {%0,%1},%2;" : "=f"(lo), "=f"(hi) : "l"(v));
}
__device__ __forceinline__ u64 f2add(u64 a, u64 b) {
    u64 r; asm("add.rn.f32x2 %0,%1,%2;" : "=l"(r) : "l"(a), "l"(b)); return r;
}
__device__ __forceinline__ u64 f2fma(u64 a, u64 b, u64 c) {
    u64 r; asm("fma.rn.f32x2 %0,%1,%2,%3;" : "=l"(r) : "l"(a), "l"(b), "l"(c)); return r;
}
__device__ __forceinline__ float sqrta(float x) {
    float r; asm("sqrt.approx.f32 %0,%1;" : "=f"(r) : "f"(x)); return r;
}
__device__ __forceinline__ float tanha(float x) {
    float r; asm("tanh.approx.f32 %0,%1;" : "=f"(r) : "f"(x)); return r;
}

__global__ void __launch_bounds__(128, 1) LDSMIXTURELQR_58445914964044_kernel(
    const float* __restrict__ xs1, const float* __restrict__ xs2,
    const float* __restrict__ init_y, const float* __restrict__ x0p,
    const float* __restrict__ Ap, const float* __restrict__ Bp,
    const float* __restrict__ g1p, const float* __restrict__ g2p,
    float* __restrict__ out, int T)
{
    // Order matters: consumer prefetch overreads past row ends; they must land
    // inside the shared block (the next array), never OOB.
    __shared__ __align__(16) float s_nx1[NSLOT][CH * 2];   // -xs1 (packed pairs)
    __shared__ __align__(16) float s_qm [NSLOT][CH * 4];   // {qh0,qh1,m0,m1}
    __shared__ __align__(16) float s_out[NSLOT][CH * 4];   // {u0,u1,n1,n1}
    __shared__ volatile int f_in_ready[NSLOT];
    __shared__ volatile int f_in_done[NSLOT];
    __shared__ volatile int f_out_ready[NSLOT];
    __shared__ volatile int f_done2[NSLOT];   // warp2 (x + u) consumed slot
    __shared__ volatile int f_done3[NSLOT];   // warp3 (y) consumed slot

    const int tid = threadIdx.x;
    if (tid < NSLOT) {
        f_in_ready[tid] = 0; f_in_done[tid] = 0;
        f_out_ready[tid] = 0; f_done2[tid] = 0; f_done3[tid] = 0;
    }
    __syncthreads();

    const int nchunk = (T + CH - 1) / CH;
    const int wid = tid >> 5;
    const int lane = tid & 31;

    if (tid == 0) {
        // ---------------- serial core ----------------
        float x  = *x0p;
        float y0 = init_y[0], y1 = init_y[1];
        float A_ = *Ap;
        float s_ = Bp[0] + Bp[1];
        float g1 = *g1p, g2 = *g2p;
        const float dt = 1.0f / 60.0f;
        const float hS = 0.5f * s_;
        const float c_ = 0.5f * (g1 + g2);
        const float dg = 0.5f * (g1 - g2);

        u64 yv   = pk2(y0, y1);
        u64 dtv  = pk2(dt, dt);
        u64 mcv  = pk2(-c_, -c_);
        u64 mdgv = pk2(-dg, -dg);

        float xc0 = fminf(fmaxf(x, -10.0f), 10.0f);
        float w0  = 1.0f / (1.0f + expf(-xc0));
        float th  = 2.0f * w0 - 1.0f;             // tanh(x0/2)
        float ah  = 0.5f * (A_ * x);              // A*(x/2)

        for (int c = 0; c < nchunk; c++) {
            const int slot = c & (NSLOT - 1);
            while (f_in_ready[slot] < c + 1) {}
            if (c >= NSLOT) {
                const int need = c - NSLOT + 1;
                while (f_done2[slot] < need) {}
                while (f_done3[slot] < need) {}
            }
            __threadfence_block();

            const int len = min(CH, T - c * CH);
            const u64*        pnx = (const u64*)s_nx1[slot];
            const ulonglong2* pqm = (const ulonglong2*)s_qm[slot];
            float4*           po  = (float4*)s_out[slot];

            if (len == CH) {
                u64 e1p = f2add(yv, pnx[0]);
                float e1lo, e1hi; upk2(e1p, e1lo, e1hi);
                u64        a_nx = pnx[1];
                ulonglong2 a_qm = pqm[0];
                u64        b_nx = pnx[2];
                ulonglong2 b_qm = pqm[1];

                #pragma unroll 8
                for (int i = 0; i < CH; i++) {
                    const u64        nxn = a_nx;   // -xs1_{i+1}
                    const ulonglong2 qm  = a_qm;   // {qh_i, m_i}
                    a_nx = b_nx; a_qm = b_qm;
                    b_nx = pnx[i + 3];             // overread -> s_qm: safe
                    b_qm = pqm[i + 2];             // overread -> s_out: safe

                    // norm / h chain (critical)
                    const float hh = e1hi * e1hi;
                    const float sq = fmaf(e1lo, e1lo, hh);
                    const float n1 = sqrta(sq);
                    const float hn = fmaf(hS, n1, ah);   // x_{i+1}/2
                    ah = A_ * hn;

                    // u_i = (m - c y) + th (qh - d y)
                    const u64 Qh = f2fma(mdgv, yv, qm.x);
                    const u64 P2 = f2fma(mcv,  yv, qm.y);
                    float qhlo, qhhi; upk2(Qh, qhlo, qhhi);
                    float p2lo, p2hi; upk2(P2, p2lo, p2hi);
                    const float ulo = fmaf(th, qhlo, p2lo);
                    const float uhi = fmaf(th, qhhi, p2hi);

                    th = tanha(hn);                      // th for next iter

                    // next e1 (chain-shortened)
                    const u64 ply = f2add(yv, nxn);      // y_i - xs1_{i+1}
                    float pllo, plhi; upk2(ply, pllo, plhi);
                    e1lo = fmaf(dt, ulo, pllo);
                    e1hi = fmaf(dt, uhi, plhi);

                    // y update (needed for Qh/P2 next iter)
                    const u64 uu = pk2(ulo, uhi);
                    yv = f2fma(dtv, uu, yv);             // y_{i+1}

                    // single store: {u0,u1,n1,n1}
                    float4 st; st.x = ulo; st.y = uhi; st.z = n1; st.w = n1;
                    po[i] = st;                          // STS.128
                }
            } else {
                for (int i = 0; i < len; i++) {
                    const u64 e1p2 = f2add(yv, pnx[i]);
                    float e1lo, e1hi; upk2(e1p2, e1lo, e1hi);
                    const float hh = e1hi * e1hi;
                    const float sq = fmaf(e1lo, e1lo, hh);
                    const float n1 = sqrta(sq);
                    const float hn = fmaf(hS, n1, ah);
                    ah = A_ * hn;
                    const ulonglong2 qm = pqm[i];
                    const u64 Qh = f2fma(mdgv, yv, qm.x);
                    const u64 P2 = f2fma(mcv,  yv, qm.y);
                    float qhlo, qhhi; upk2(Qh, qhlo, qhhi);
                    float p2lo, p2hi; upk2(P2, p2lo, p2hi);
                    const float ulo = fmaf(th, qhlo, p2lo);
                    const float uhi = fmaf(th, qhhi, p2hi);
                    th = tanha(hn);
                    const u64 uu = pk2(ulo, uhi);
                    yv = f2fma(dtv, uu, yv);
                    float4 st; st.x = ulo; st.y = uhi; st.z = n1; st.w = n1;
                    po[i] = st;
                }
            }
            __threadfence_block();
            f_out_ready[slot] = c + 1;
            f_in_done[slot]   = c + 1;
        }
    } else if (wid == 1) {
        // ---------------- producer: GMEM -> SMEM input ring ------------------
        const float g1 = *g1p, g2 = *g2p;
        const float hg1 = 0.5f * g1, hg2 = 0.5f * g2;
        for (int c = 0; c < nchunk; c++) {
            const int slot = c & (NSLOT - 1);
            if (c >= NSLOT) { while (f_in_done[slot] < c - NSLOT + 1) {} }
            const int base = c * CH;
            const int len  = min(CH, T - base);
            if (len == CH) {
                const float4* g1v4 = (const float4*)(xs1 + (size_t)base * 2);
                const float4* g2v4 = (const float4*)(xs2 + (size_t)base * 2);
                float4* smn = (float4*)s_nx1[slot];
                float4* smq = (float4*)s_qm[slot];
                #pragma unroll
                for (int k = lane; k < CH / 2; k += 32) {   // k covers 2 steps
                    const float4 v1 = __ldg(&g1v4[k]);
                    const float4 v2 = __ldg(&g2v4[k]);
                    float4 n; n.x = -v1.x; n.y = -v1.y; n.z = -v1.z; n.w = -v1.w;
                    smn[k] = n;
                    float4 qa;
                    qa.x = hg1 * v1.x - hg2 * v2.x;
                    qa.y = hg1 * v1.y - hg2 * v2.y;
                    qa.z = hg1 * v1.x + hg2 * v2.x;
                    qa.w = hg1 * v1.y + hg2 * v2.y;
                    smq[2 * k] = qa;
                    float4 qb;
                    qb.x = hg1 * v1.z - hg2 * v2.z;
                    qb.y = hg1 * v1.w - hg2 * v2.w;
                    qb.z = hg1 * v1.z + hg2 * v2.z;
                    qb.w = hg1 * v1.w + hg2 * v2.w;
                    smq[2 * k + 1] = qb;
                }
            } else {
                for (int k = lane; k < len; k += 32) {
                    const float a0 = xs1[(size_t)(base + k) * 2];
                    const float a1 = xs1[(size_t)(base + k) * 2 + 1];
                    const float b0 = xs2[(size_t)(base + k) * 2];
                    const float b1 = xs2[(size_t)(base + k) * 2 + 1];
                    s_nx1[slot][2 * k]     = -a0;
                    s_nx1[slot][2 * k + 1] = -a1;
                    s_qm[slot][4 * k]     = hg1 * a0 - hg2 * b0;
                    s_qm[slot][4 * k + 1] = hg1 * a1 - hg2 * b1;
                    s_qm[slot][4 * k + 2] = hg1 * a0 + hg2 * b0;
                    s_qm[slot][4 * k + 3] = hg1 * a1 + hg2 * b1;
                }
            }
            __threadfence_block();
            __syncwarp();
            if (lane == 0) f_in_ready[slot] = c + 1;
        }
    } else if (wid == 2) {
        // ------- warp2: lane0 x-reconstruct + STG; lanes 1-31 copy u ---------
        const int TP1 = T + 1;
        float A_ = *Ap;
        float s_ = Bp[0] + Bp[1];
        float axr = A_ * (*x0p);               // A*x0 (matches serial seq)
        float* outx = out + 1;                 // x_full[1+t]
        float* outu = out + 3 * TP1;           // us[t]  (ODD offset: 32-bit only)
        if (lane == 0) out[0] = *x0p;          // x_full[0]
        for (int c = 0; c < nchunk; c++) {
            const int slot = c & (NSLOT - 1);
            while (f_out_ready[slot] < c + 1) {}
            __threadfence_block();
            const int base = c * CH;
            const int len  = min(CH, T - base);
            const float* ps = s_out[slot];
            if (lane == 0) {
                // serial x reconstruction: xn = fmaf(s, n1, A*x_prev)
                for (int i = 0; i < len; i++) {
                    const float n1 = ps[4 * i + 2];
                    const float xn = fmaf(s_, n1, axr);
                    axr = A_ * xn;
                    outx[base + i] = xn;
                }
            } else {
                for (int k = lane - 1; k < len; k += 31) {
                    outu[2 * (size_t)(base + k)]     = ps[4 * k];
                    outu[2 * (size_t)(base + k) + 1] = ps[4 * k + 1];
                }
            }
            __syncwarp();
            if (lane == 0) f_done2[slot] = c + 1;
        }
    } else {
        // ------- warp3: lane0 y-reconstruct (bit-identical f2fma) + STG ------
        const int TP1 = T + 1;
        const float dt = 1.0f / 60.0f;
        u64 dtv = pk2(dt, dt);
        u64 yvr = pk2(init_y[0], init_y[1]);
        float* outy = out + TP1 + 2;           // y_full[1+t] (ODD offset: 32-bit only)
        if (lane == 0) {
            out[TP1]     = init_y[0];          // y_full[0]
            out[TP1 + 1] = init_y[1];
        }
        for (int c = 0; c < nchunk; c++) {
            const int slot = c & (NSLOT - 1);
            while (f_out_ready[slot] < c + 1) {}
            __threadfence_block();
            const int base = c * CH;
            const int len  = min(CH, T - base);
            const u64* pu = (const u64*)s_out[slot];   // u at entry offset 0
            if (lane == 0) {
                for (int i = 0; i < len; i++) {
                    const u64 uu = pu[2 * i];          // {u0,u1}
                    yvr = f2fma(dtv, uu, yvr);         // identical to serial
                    float ylo, yhi; upk2(yvr, ylo, yhi);
                    outy[2 * (size_t)(base + i)]     = ylo;   // STG.32 (aligned)
                    outy[2 * (size_t)(base + i) + 1] = yhi;   // STG.32
                }
            }
            __syncwarp();
            if (lane == 0) f_done3[slot] = c + 1;
        }
    }
}

extern "C" void kernel_launch(void* const* d_in, const int* in_sizes, int n_in,
                              void* d_out, int out_size) {
    // Input order (confirmed): [xstar1, xstar2, init_y, x0, A, B, gain1, gain2]
    const float* xs1    = (const float*)d_in[0];
    const float* xs2    = (const float*)d_in[1];
    const float* init_y = (const float*)d_in[2];
    const float* x0     = (const float*)d_in[3];
    const float* A      = (const float*)d_in[4];
    const float* B      = (const float*)d_in[5];
    const float* g1     = (const float*)d_in[6];
    const float* g2     = (const float*)d_in[7];
    const int T = in_sizes[0] / 2;
    LDSMIXTURELQR_58445914964044_kernel<<<1, 128>>>(
        xs1, xs2, init_y, x0, A, B, g1, g2, (float*)d_out, T);
}

// round 11
// speedup vs baseline: 2.4804x; 1.0530x over previous
#include <cuda_runtime.h>
#include <math.h>

// LDSMIXTURELQR: sequential nonlinear scan, T=131072 steps.
// 4-warp specialization (128 threads):
//   warp0 lane0 : serial core — ALL-SCALAR recurrence, stores {u0,u1,n1} per step
//   warp1       : producer — GMEM -> SMEM ring (-xs1, qh, m precomputed)
//   warp2       : lane0 reconstructs x from n1 (bit-identical) + STG;
//                 lanes 1-31 copy u SMEM -> GMEM (scalar: us base is odd-offset)
//   warp3       : lane0 reconstructs y from u (per-lane fma == scalar fmaf) + STG.32
//
// NOTE on alignment: y_full starts at out+(T+1), us at out+3(T+1) — both ODD
// float offsets for even T. All GMEM stores to these regions must be 32-bit.
//
// Serial-core algebra (exact identity with w=(1+th)/2, th=tanh(x/2)):
//   u_t = (m_t - c*y_t) + th*(qh_t - d*y_t);  c=(g1+g2)/2, d=(g1-g2)/2
//   e1_t = y_t - xs1_t;  n1 = sqrt(e1.e1)
//   h' = A*h + (s/2)*n1  (h = x/2);  y' = y + dt*u

#define CH    256
#define NSLOT 4

typedef unsigned long long u64;

__device__ __forceinline__ u64 pk2(float lo, float hi) {
    u64 r; asm("mov.b64 %0,{%1,%2};" : "=l"(r) : "f"(lo), "f"(hi)); return r;
}
__device__ __forceinline__ void upk2(u64 v, float& lo, float& hi) {
    asm("mov.b64 {%0,%1},%2;" : "=f"(lo), "=f"(hi) : "l"(v));
}
__device__ __forceinline__ u64 f2fma(u64 a, u64 b, u64 c) {
    u64 r; asm("fma.rn.f32x2 %0,%1,%2,%3;" : "=l"(r) : "l"(a), "l"(b), "l"(c)); return r;
}
__device__ __forceinline__ float sqrta(float x) {
    float r; asm("sqrt.approx.f32 %0,%1;" : "=f"(r) : "f"(x)); return r;
}
__device__ __forceinline__ float tanha(float x) {
    float r; asm("tanh.approx.f32 %0,%1;" : "=f"(r) : "f"(x)); return r;
}

__global__ void __launch_bounds__(128, 1) LDSMIXTURELQR_58445914964044_kernel(
    const float* __restrict__ xs1, const float* __restrict__ xs2,
    const float* __restrict__ init_y, const float* __restrict__ x0p,
    const float* __restrict__ Ap, const float* __restrict__ Bp,
    const float* __restrict__ g1p, const float* __restrict__ g2p,
    float* __restrict__ out, int T)
{
    // Order matters: consumer prefetch overreads past row ends; they must land
    // inside the shared block (the next array), never OOB.
    __shared__ __align__(16) float s_nx1[NSLOT][CH * 2];   // -xs1 pairs
    __shared__ __align__(16) float s_qm [NSLOT][CH * 4];   // {qh0,qh1,m0,m1}
    __shared__ __align__(16) float s_out[NSLOT][CH * 4];   // {u0,u1,n1,n1}
    __shared__ volatile int f_in_ready[NSLOT];
    __shared__ volatile int f_in_done[NSLOT];
    __shared__ volatile int f_out_ready[NSLOT];
    __shared__ volatile int f_done2[NSLOT];
    __shared__ volatile int f_done3[NSLOT];

    const int tid = threadIdx.x;
    if (tid < NSLOT) {
        f_in_ready[tid] = 0; f_in_done[tid] = 0;
        f_out_ready[tid] = 0; f_done2[tid] = 0; f_done3[tid] = 0;
    }
    __syncthreads();

    const int nchunk = (T + CH - 1) / CH;
    const int wid = tid >> 5;
    const int lane = tid & 31;

    if (tid == 0) {
        // ---------------- serial core (all scalar) ----------------
        float x  = *x0p;
        float y0 = init_y[0], y1 = init_y[1];
        float A_ = *Ap;
        float s_ = Bp[0] + Bp[1];
        float g1 = *g1p, g2 = *g2p;
        const float dt  = 1.0f / 60.0f;
        const float hS  = 0.5f * s_;
        const float mc  = -0.5f * (g1 + g2);
        const float mdg = -0.5f * (g1 - g2);

        float xc0 = fminf(fmaxf(x, -10.0f), 10.0f);
        float w0  = 1.0f / (1.0f + expf(-xc0));
        float th  = 2.0f * w0 - 1.0f;             // tanh(x0/2)
        float ah  = 0.5f * (A_ * x);              // A*(x/2)

        for (int c = 0; c < nchunk; c++) {
            const int slot = c & (NSLOT - 1);
            while (f_in_ready[slot] < c + 1) {}
            if (c >= NSLOT) {
                const int need = c - NSLOT + 1;
                while (f_done2[slot] < need) {}
                while (f_done3[slot] < need) {}
            }
            __threadfence_block();

            const int len = min(CH, T - c * CH);
            const float2* pnx = (const float2*)s_nx1[slot];
            const float4* pqm = (const float4*)s_qm[slot];
            float4*       po  = (float4*)s_out[slot];

            if (len == CH) {
                // distance-2 prefetch (overreads land in adjacent SMEM: safe)
                float2 a_nx = pnx[0]; float4 a_qm = pqm[0];
                float2 b_nx = pnx[1]; float4 b_qm = pqm[1];

                #pragma unroll 16
                for (int i = 0; i < CH; i++) {
                    const float2 nx = a_nx;   // {-xs1_0, -xs1_1} at step i
                    const float4 qm = a_qm;   // {qh0, qh1, m0, m1} at step i
                    a_nx = b_nx; a_qm = b_qm;
                    b_nx = pnx[i + 2];
                    b_qm = pqm[i + 2];

                    // e1_i = y_i - xs1_i ; n1 = |e1|
                    const float e1lo = y0 + nx.x;
                    const float e1hi = y1 + nx.y;
                    const float hh = e1hi * e1hi;
                    const float sq = fmaf(e1lo, e1lo, hh);
                    const float n1 = sqrta(sq);
                    const float hn = fmaf(hS, n1, ah);   // x_{i+1}/2
                    ah = A_ * hn;

                    // u_i = (m - c y) + th (qh - d y)   [all scalar]
                    const float t0 = fmaf(mdg, y0, qm.x);
                    const float t1 = fmaf(mdg, y1, qm.y);
                    const float p0 = fmaf(mc,  y0, qm.z);
                    const float p1 = fmaf(mc,  y1, qm.w);
                    const float u0 = fmaf(th, t0, p0);
                    const float u1 = fmaf(th, t1, p1);

                    th = tanha(hn);                      // th for next iter

                    // y_{i+1}
                    y0 = fmaf(dt, u0, y0);
                    y1 = fmaf(dt, u1, y1);

                    float4 st; st.x = u0; st.y = u1; st.z = n1; st.w = n1;
                    po[i] = st;                          // STS.128
                }
            } else {
                for (int i = 0; i < len; i++) {
                    const float2 nx = pnx[i];
                    const float4 qm = pqm[i];
                    const float e1lo = y0 + nx.x;
                    const float e1hi = y1 + nx.y;
                    const float hh = e1hi * e1hi;
                    const float sq = fmaf(e1lo, e1lo, hh);
                    const float n1 = sqrta(sq);
                    const float hn = fmaf(hS, n1, ah);
                    ah = A_ * hn;
                    const float t0 = fmaf(mdg, y0, qm.x);
                    const float t1 = fmaf(mdg, y1, qm.y);
                    const float p0 = fmaf(mc,  y0, qm.z);
                    const float p1 = fmaf(mc,  y1, qm.w);
                    const float u0 = fmaf(th, t0, p0);
                    const float u1 = fmaf(th, t1, p1);
                    th = tanha(hn);
                    y0 = fmaf(dt, u0, y0);
                    y1 = fmaf(dt, u1, y1);
                    float4 st; st.x = u0; st.y = u1; st.z = n1; st.w = n1;
                    po[i] = st;
                }
            }
            __threadfence_block();
            f_out_ready[slot] = c + 1;
            f_in_done[slot]   = c + 1;
        }
    } else if (wid == 1) {
        // ---------------- producer: GMEM -> SMEM input ring ------------------
        const float g1 = *g1p, g2 = *g2p;
        const float hg1 = 0.5f * g1, hg2 = 0.5f * g2;
        for (int c = 0; c < nchunk; c++) {
            const int slot = c & (NSLOT - 1);
            if (c >= NSLOT) { while (f_in_done[slot] < c - NSLOT + 1) {} }
            const int base = c * CH;
            const int len  = min(CH, T - base);
            if (len == CH) {
                const float4* g1v4 = (const float4*)(xs1 + (size_t)base * 2);
                const float4* g2v4 = (const float4*)(xs2 + (size_t)base * 2);
                float4* smn = (float4*)s_nx1[slot];
                float4* smq = (float4*)s_qm[slot];
                #pragma unroll
                for (int k = lane; k < CH / 2; k += 32) {   // k covers 2 steps
                    const float4 v1 = __ldg(&g1v4[k]);
                    const float4 v2 = __ldg(&g2v4[k]);
                    float4 n; n.x = -v1.x; n.y = -v1.y; n.z = -v1.z; n.w = -v1.w;
                    smn[k] = n;
                    float4 qa;
                    qa.x = hg1 * v1.x - hg2 * v2.x;
                    qa.y = hg1 * v1.y - hg2 * v2.y;
                    qa.z = hg1 * v1.x + hg2 * v2.x;
                    qa.w = hg1 * v1.y + hg2 * v2.y;
                    smq[2 * k] = qa;
                    float4 qb;
                    qb.x = hg1 * v1.z - hg2 * v2.z;
                    qb.y = hg1 * v1.w - hg2 * v2.w;
                    qb.z = hg1 * v1.z + hg2 * v2.z;
                    qb.w = hg1 * v1.w + hg2 * v2.w;
                    smq[2 * k + 1] = qb;
                }
            } else {
                for (int k = lane; k < len; k += 32) {
                    const float a0 = xs1[(size_t)(base + k) * 2];
                    const float a1 = xs1[(size_t)(base + k) * 2 + 1];
                    const float b0 = xs2[(size_t)(base + k) * 2];
                    const float b1 = xs2[(size_t)(base + k) * 2 + 1];
                    s_nx1[slot][2 * k]     = -a0;
                    s_nx1[slot][2 * k + 1] = -a1;
                    s_qm[slot][4 * k]     = hg1 * a0 - hg2 * b0;
                    s_qm[slot][4 * k + 1] = hg1 * a1 - hg2 * b1;
                    s_qm[slot][4 * k + 2] = hg1 * a0 + hg2 * b0;
                    s_qm[slot][4 * k + 3] = hg1 * a1 + hg2 * b1;
                }
            }
            __threadfence_block();
            __syncwarp();
            if (lane == 0) f_in_ready[slot] = c + 1;
        }
    } else if (wid == 2) {
        // ------- warp2: lane0 x-reconstruct + STG; lanes 1-31 copy u ---------
        const int TP1 = T + 1;
        float A_ = *Ap;
        float s_ = Bp[0] + Bp[1];
        float axr = A_ * (*x0p);               // A*x0 (matches serial seq)
        float* outx = out + 1;                 // x_full[1+t]
        float* outu = out + 3 * TP1;           // us[t]  (ODD offset: 32-bit only)
        if (lane == 0) out[0] = *x0p;          // x_full[0]
        for (int c = 0; c < nchunk; c++) {
            const int slot = c & (NSLOT - 1);
            while (f_out_ready[slot] < c + 1) {}
            __threadfence_block();
            const int base = c * CH;
            const int len  = min(CH, T - base);
            const float* ps = s_out[slot];
            if (lane == 0) {
                for (int i = 0; i < len; i++) {
                    const float n1 = ps[4 * i + 2];
                    const float xn = fmaf(s_, n1, axr);
                    axr = A_ * xn;
                    outx[base + i] = xn;
                }
            } else {
                for (int k = lane - 1; k < len; k += 31) {
                    outu[2 * (size_t)(base + k)]     = ps[4 * k];
                    outu[2 * (size_t)(base + k) + 1] = ps[4 * k + 1];
                }
            }
            __syncwarp();
            if (lane == 0) f_done2[slot] = c + 1;
        }
    } else {
        // ------- warp3: lane0 y-reconstruct (per-lane fma == scalar) + STG ---
        const int TP1 = T + 1;
        const float dt = 1.0f / 60.0f;
        u64 dtv = pk2(dt, dt);
        u64 yvr = pk2(init_y[0], init_y[1]);
        float* outy = out + TP1 + 2;           // y_full[1+t] (ODD offset: 32-bit only)
        if (lane == 0) {
            out[TP1]     = init_y[0];          // y_full[0]
            out[TP1 + 1] = init_y[1];
        }
        for (int c = 0; c < nchunk; c++) {
            const int slot = c & (NSLOT - 1);
            while (f_out_ready[slot] < c + 1) {}
            __threadfence_block();
            const int base = c * CH;
            const int len  = min(CH, T - base);
            const u64* pu = (const u64*)s_out[slot];   // u at entry offset 0
            if (lane == 0) {
                for (int i = 0; i < len; i++) {
                    const u64 uu = pu[2 * i];          // {u0,u1}
                    yvr = f2fma(dtv, uu, yvr);         // per-lane == scalar fmaf
                    float ylo, yhi; upk2(yvr, ylo, yhi);
                    outy[2 * (size_t)(base + i)]     = ylo;   // STG.32
                    outy[2 * (size_t)(base + i) + 1] = yhi;   // STG.32
                }
            }
            __syncwarp();
            if (lane == 0) f_done3[slot] = c + 1;
        }
    }
}

extern "C" void kernel_launch(void* const* d_in, const int* in_sizes, int n_in,
                              void* d_out, int out_size) {
    // Input order (confirmed): [xstar1, xstar2, init_y, x0, A, B, gain1, gain2]
    const float* xs1    = (const float*)d_in[0];
    const float* xs2    = (const float*)d_in[1];
    const float* init_y = (const float*)d_in[2];
    const float* x0     = (const float*)d_in[3];
    const float* A      = (const float*)d_in[4];
    const float* B      = (const float*)d_in[5];
    const float* g1     = (const float*)d_in[6];
    const float* g2     = (const float*)d_in[7];
    const int T = in_sizes[0] / 2;
    LDSMIXTURELQR_58445914964044_kernel<<<1, 128>>>(
        xs1, xs2, init_y, x0, A, B, g1, g2, (float*)d_out, T);
}